// round 1
// baseline (speedup 1.0000x reference)
#include <cuda_runtime.h>
#include <math.h>

#define BB 32
#define CC 3
#define IMGSZ 224
#define NP 14
#define PS 16
#define DIM 768
#define NHD 12
#define HDD 64
#define LL 12
#define NCLS 1000
#define SS 197
#define MLPD 3072
#define RTOT (BB*SS)      /* 6304 rows */
#define PTOT (BB*NP*NP)   /* 6272 patch rows */

// ---------------- scratch (device globals; no allocations) ----------------
__device__ float g_patches[PTOT*DIM];
__device__ float g_x[RTOT*DIM];
__device__ float g_h[RTOT*DIM];
__device__ float g_q[RTOT*DIM];
__device__ float g_k[RTOT*DIM];
__device__ float g_v[RTOT*DIM];
__device__ float g_mlp[(size_t)RTOT*MLPD];
__device__ float g_logits[BB*NCLS];

// ---------------- patchify: (B,C,H,W) -> (B,196,768) ----------------
__global__ void patchify_kernel(const float* __restrict__ img, float* __restrict__ out) {
    int idx = blockIdx.x * blockDim.x + threadIdx.x;
    if (idx >= PTOT * DIM) return;
    int f = idx % DIM;
    int t = (idx / DIM) % (NP * NP);
    int b = idx / (DIM * NP * NP);
    int c  = f >> 8;          // f = c*256 + iy*16 + ix
    int iy = (f >> 4) & 15;
    int ix = f & 15;
    int py = t / NP, px = t % NP;
    out[idx] = img[(((size_t)b * CC + c) * IMGSZ + py * PS + iy) * IMGSZ + px * PS + ix];
}

// ---------------- assemble x = concat(cls, tokens) + pos ----------------
__global__ void assemble_kernel(const float* __restrict__ tok, const float* __restrict__ cls,
                                const float* __restrict__ pos, float* __restrict__ x) {
    int idx = blockIdx.x * blockDim.x + threadIdx.x;
    if (idx >= RTOT * DIM) return;
    int d = idx % DIM;
    int s = (idx / DIM) % SS;
    int b = idx / (DIM * SS);
    float v = (s == 0) ? cls[d] : tok[((size_t)b * (NP * NP) + (s - 1)) * DIM + d];
    x[idx] = v + pos[s * DIM + d];
}

// ---------------- generic SGEMM: C(MxN) = A(MxK, lda) @ B(KxN) + bias ----------------
// MODE 0: C = acc + bias; MODE 1: C = gelu(acc + bias); MODE 2: C += acc + bias
template<int MODE>
__global__ void sgemm_kernel(const float* __restrict__ A, const float* __restrict__ B,
                             const float* __restrict__ bias, float* __restrict__ C,
                             int M, int N, int K, int lda) {
    __shared__ float As[8][128];
    __shared__ float Bs[8][128];
    int tid = threadIdx.x;
    int tx = tid & 15, ty = tid >> 4;
    int row0 = blockIdx.y * 128, col0 = blockIdx.x * 128;
    int arow = tid >> 1, acol = (tid & 1) * 4;
    int brow = tid >> 5, bcol = (tid & 31) * 4;

    float acc[8][8];
#pragma unroll
    for (int i = 0; i < 8; i++)
#pragma unroll
        for (int j = 0; j < 8; j++) acc[i][j] = 0.f;

    for (int k0 = 0; k0 < K; k0 += 8) {
        float4 av = make_float4(0.f, 0.f, 0.f, 0.f);
        if (row0 + arow < M)
            av = *(const float4*)(A + (size_t)(row0 + arow) * lda + k0 + acol);
        As[acol + 0][arow] = av.x;
        As[acol + 1][arow] = av.y;
        As[acol + 2][arow] = av.z;
        As[acol + 3][arow] = av.w;

        int bc = col0 + bcol;
        float4 bv = make_float4(0.f, 0.f, 0.f, 0.f);
        if (bc + 3 < N) {
            bv = *(const float4*)(B + (size_t)(k0 + brow) * N + bc);
        } else {
            float tmp[4] = {0.f, 0.f, 0.f, 0.f};
            for (int i = 0; i < 4; i++)
                if (bc + i < N) tmp[i] = B[(size_t)(k0 + brow) * N + bc + i];
            bv = make_float4(tmp[0], tmp[1], tmp[2], tmp[3]);
        }
        *(float4*)&Bs[brow][bcol] = bv;
        __syncthreads();

#pragma unroll
        for (int kk = 0; kk < 8; kk++) {
            float a[8], bb[8];
#pragma unroll
            for (int i = 0; i < 8; i++) a[i] = As[kk][ty * 8 + i];
#pragma unroll
            for (int j = 0; j < 8; j++) bb[j] = Bs[kk][tx * 8 + j];
#pragma unroll
            for (int i = 0; i < 8; i++)
#pragma unroll
                for (int j = 0; j < 8; j++) acc[i][j] = fmaf(a[i], bb[j], acc[i][j]);
        }
        __syncthreads();
    }

#pragma unroll
    for (int i = 0; i < 8; i++) {
        int r = row0 + ty * 8 + i;
        if (r >= M) continue;
#pragma unroll
        for (int j = 0; j < 8; j++) {
            int c = col0 + tx * 8 + j;
            if (c >= N) continue;
            float v = acc[i][j] + bias[c];
            if (MODE == 1) v = 0.5f * v * (1.f + erff(v * 0.70710678118654752f));
            if (MODE == 2) v += C[(size_t)r * N + c];
            C[(size_t)r * N + c] = v;
        }
    }
}

// ---------------- LayerNorm over D=768, one block per row ----------------
__global__ void ln_kernel(const float* __restrict__ x, const float* __restrict__ g,
                          const float* __restrict__ be, float* __restrict__ o) {
    int row = blockIdx.x, tid = threadIdx.x;
    const float* xr = x + (size_t)row * DIM;
    float v0 = xr[tid], v1 = xr[tid + 256], v2 = xr[tid + 512];
    __shared__ float red[32];
    int lane = tid & 31, w = tid >> 5;

    float s = v0 + v1 + v2;
#pragma unroll
    for (int off = 16; off; off >>= 1) s += __shfl_xor_sync(0xffffffffu, s, off);
    if (lane == 0) red[w] = s;
    __syncthreads();
    float tot = (lane < 8) ? red[lane] : 0.f;
#pragma unroll
    for (int off = 16; off; off >>= 1) tot += __shfl_xor_sync(0xffffffffu, tot, off);
    float mean = tot * (1.f / 768.f);

    float d0 = v0 - mean, d1 = v1 - mean, d2 = v2 - mean;
    float sq = d0 * d0 + d1 * d1 + d2 * d2;
#pragma unroll
    for (int off = 16; off; off >>= 1) sq += __shfl_xor_sync(0xffffffffu, sq, off);
    __syncthreads();
    if (lane == 0) red[w] = sq;
    __syncthreads();
    float tot2 = (lane < 8) ? red[lane] : 0.f;
#pragma unroll
    for (int off = 16; off; off >>= 1) tot2 += __shfl_xor_sync(0xffffffffu, tot2, off);
    float inv = rsqrtf(tot2 * (1.f / 768.f) + 1e-5f);

    float* orow = o + (size_t)row * DIM;
    orow[tid]       = d0 * inv * g[tid]       + be[tid];
    orow[tid + 256] = d1 * inv * g[tid + 256] + be[tid + 256];
    orow[tid + 512] = d2 * inv * g[tid + 512] + be[tid + 512];
}

// ---------------- per-head QKV projection: 64x64 GEMMs ----------------
__global__ void qkv_kernel(const float* __restrict__ h,
                           const float* __restrict__ Wq, const float* __restrict__ bq,
                           const float* __restrict__ Wk, const float* __restrict__ bk,
                           const float* __restrict__ Wv, const float* __restrict__ bv,
                           float* __restrict__ q, float* __restrict__ k, float* __restrict__ v) {
    __shared__ float Xs[64 * 64];
    __shared__ float Ws[64 * 64];
    int hd = blockIdx.y;
    int r0 = blockIdx.x * 64;
    int tid = threadIdx.x;

    for (int i = tid; i < 4096; i += 256) {
        int rl = i >> 6, e = i & 63;
        int row = r0 + rl;
        Xs[i] = (row < RTOT) ? h[(size_t)row * DIM + hd * HDD + e] : 0.f;
    }

    int rg = tid >> 4, eg = tid & 15;
    const float* Wm[3] = {Wq + (size_t)hd * HDD * HDD, Wk + (size_t)hd * HDD * HDD, Wv + (size_t)hd * HDD * HDD};
    const float* bm[3] = {bq + hd * HDD, bk + hd * HDD, bv + hd * HDD};
    float* om[3] = {q, k, v};

    for (int m = 0; m < 3; m++) {
        __syncthreads();
        for (int i = tid; i < 4096; i += 256) Ws[i] = Wm[m][i];
        __syncthreads();
        float acc[4][4];
#pragma unroll
        for (int i = 0; i < 4; i++)
#pragma unroll
            for (int j = 0; j < 4; j++) acc[i][j] = 0.f;
#pragma unroll 16
        for (int kk = 0; kk < 64; kk++) {
            float a[4], bb[4];
#pragma unroll
            for (int i = 0; i < 4; i++) a[i] = Xs[(rg * 4 + i) * 64 + kk];
#pragma unroll
            for (int j = 0; j < 4; j++) bb[j] = Ws[kk * 64 + eg * 4 + j];
#pragma unroll
            for (int i = 0; i < 4; i++)
#pragma unroll
                for (int j = 0; j < 4; j++) acc[i][j] = fmaf(a[i], bb[j], acc[i][j]);
        }
        for (int i = 0; i < 4; i++) {
            int row = r0 + rg * 4 + i;
            if (row >= RTOT) continue;
            int b = row / SS, s = row % SS;
            float* op = om[m] + (((size_t)b * NHD + hd) * SS + s) * HDD + eg * 4;
            for (int j = 0; j < 4; j++) op[j] = acc[i][j] + bm[m][eg * 4 + j];
        }
    }
}

// ---------------- fused attention: scores+softmax+PV, x += out ----------------
// grid: (7 q-tiles of 32, B*NH); dynamic smem ~150KB
#define KS_STRIDE 256
#define SC_STRIDE 208
#define ATTN_SMEM ((64*KS_STRIDE + SS*HDD + 64*32 + 32*SC_STRIDE) * 4)

__global__ void attn_kernel(const float* __restrict__ q, const float* __restrict__ k,
                            const float* __restrict__ v, float* __restrict__ x) {
    extern __shared__ float sm[];
    float* Ks  = sm;                        // [64][256] e-major (zero padded)
    float* Vs  = Ks + 64 * KS_STRIDE;       // [197][64]
    float* Qs  = Vs + SS * HDD;             // [64][32]  e-major
    float* Ssc = Qs + 64 * 32;              // [32][208]

    int bh = blockIdx.y;
    int b = bh / NHD, hh = bh % NHD;
    int qt = blockIdx.x;
    int tid = threadIdx.x;

    const float* kb = k + (size_t)bh * SS * HDD;
    const float* vb = v + (size_t)bh * SS * HDD;
    const float* qb = q + (size_t)bh * SS * HDD;

    for (int i = tid; i < 64 * KS_STRIDE; i += 256) Ks[i] = 0.f;
    __syncthreads();
    for (int i = tid; i < SS * HDD; i += 256) {
        int t = i >> 6, e = i & 63;
        Ks[e * KS_STRIDE + t] = kb[i];
        Vs[i] = vb[i];
    }
    for (int i = tid; i < 32 * 64; i += 256) {
        int e = i >> 5, qi = i & 31;
        int s = qt * 32 + qi;
        Qs[e * 32 + qi] = (s < SS) ? qb[(size_t)s * HDD + e] : 0.f;
    }
    __syncthreads();

    // QK^T: warp qg handles 4 queries; lane kg handles 8 keys
    int qg = tid >> 5;   // 0..7
    int kg = tid & 31;   // keys kg*8..kg*8+7
    {
        float acc[4][8];
#pragma unroll
        for (int i = 0; i < 4; i++)
#pragma unroll
            for (int j = 0; j < 8; j++) acc[i][j] = 0.f;
#pragma unroll 8
        for (int e = 0; e < 64; e++) {
            float4 a  = *(float4*)&Qs[e * 32 + qg * 4];
            float4 b0 = *(float4*)&Ks[e * KS_STRIDE + kg * 8];
            float4 b1 = *(float4*)&Ks[e * KS_STRIDE + kg * 8 + 4];
            float av[4] = {a.x, a.y, a.z, a.w};
            float bv8[8] = {b0.x, b0.y, b0.z, b0.w, b1.x, b1.y, b1.z, b1.w};
#pragma unroll
            for (int i = 0; i < 4; i++)
#pragma unroll
                for (int j = 0; j < 8; j++) acc[i][j] = fmaf(av[i], bv8[j], acc[i][j]);
        }
        for (int i = 0; i < 4; i++)
            for (int j = 0; j < 8; j++) {
                int t = kg * 8 + j;
                if (t < SS) Ssc[(qg * 4 + i) * SC_STRIDE + t] = acc[i][j] * 0.125f;
            }
    }
    __syncthreads();

    // softmax: warp w -> rows w*4 .. w*4+3
    int lane = tid & 31, w = tid >> 5;
    for (int r = w * 4; r < w * 4 + 4; r++) {
        float mx = -1e30f;
        for (int t = lane; t < SS; t += 32) mx = fmaxf(mx, Ssc[r * SC_STRIDE + t]);
#pragma unroll
        for (int off = 16; off; off >>= 1) mx = fmaxf(mx, __shfl_xor_sync(0xffffffffu, mx, off));
        float sum = 0.f;
        for (int t = lane; t < SS; t += 32) {
            float p = expf(Ssc[r * SC_STRIDE + t] - mx);
            Ssc[r * SC_STRIDE + t] = p;
            sum += p;
        }
#pragma unroll
        for (int off = 16; off; off >>= 1) sum += __shfl_xor_sync(0xffffffffu, sum, off);
        float invs = 1.f / sum;
        for (int t = lane; t < SS; t += 32) Ssc[r * SC_STRIDE + t] *= invs;
    }
    __syncthreads();

    // PV: thread -> 2 queries x 4 dims
    int qg2 = tid >> 4;       // queries qg2*2, qg2*2+1
    int dg = tid & 15;        // dims dg*4..dg*4+3
    float o0[4] = {0.f, 0.f, 0.f, 0.f}, o1[4] = {0.f, 0.f, 0.f, 0.f};
    int q0 = qg2 * 2;
    for (int t = 0; t < SS; t++) {
        float p0 = Ssc[q0 * SC_STRIDE + t];
        float p1 = Ssc[(q0 + 1) * SC_STRIDE + t];
        float4 vv = *(float4*)&Vs[t * 64 + dg * 4];
        o0[0] = fmaf(p0, vv.x, o0[0]); o0[1] = fmaf(p0, vv.y, o0[1]);
        o0[2] = fmaf(p0, vv.z, o0[2]); o0[3] = fmaf(p0, vv.w, o0[3]);
        o1[0] = fmaf(p1, vv.x, o1[0]); o1[1] = fmaf(p1, vv.y, o1[1]);
        o1[2] = fmaf(p1, vv.z, o1[2]); o1[3] = fmaf(p1, vv.w, o1[3]);
    }
    int s0 = qt * 32 + q0;
    if (s0 < SS) {
        float4* px = (float4*)&x[((size_t)(b * SS + s0)) * DIM + hh * HDD + dg * 4];
        float4 cur = *px;
        cur.x += o0[0]; cur.y += o0[1]; cur.z += o0[2]; cur.w += o0[3];
        *px = cur;
    }
    if (s0 + 1 < SS) {
        float4* px = (float4*)&x[((size_t)(b * SS + s0 + 1)) * DIM + hh * HDD + dg * 4];
        float4 cur = *px;
        cur.x += o1[0]; cur.y += o1[1]; cur.z += o1[2]; cur.w += o1[3];
        *px = cur;
    }
}

// ---------------- final softmax over 1000 classes ----------------
__global__ void softmax_out_kernel(const float* __restrict__ logits, float* __restrict__ out) {
    int b = blockIdx.x, tid = threadIdx.x;
    int lane = tid & 31, w = tid >> 5;
    __shared__ float red[32];
    const float* lr = logits + (size_t)b * NCLS;

    float mx = -1e30f;
    for (int i = tid; i < NCLS; i += 256) mx = fmaxf(mx, lr[i]);
#pragma unroll
    for (int off = 16; off; off >>= 1) mx = fmaxf(mx, __shfl_xor_sync(0xffffffffu, mx, off));
    if (lane == 0) red[w] = mx;
    __syncthreads();
    float gm = (lane < 8) ? red[lane] : -1e30f;
#pragma unroll
    for (int off = 16; off; off >>= 1) gm = fmaxf(gm, __shfl_xor_sync(0xffffffffu, gm, off));

    float sum = 0.f;
    for (int i = tid; i < NCLS; i += 256) sum += expf(lr[i] - gm);
#pragma unroll
    for (int off = 16; off; off >>= 1) sum += __shfl_xor_sync(0xffffffffu, sum, off);
    __syncthreads();
    if (lane == 0) red[w] = sum;
    __syncthreads();
    float gs = (lane < 8) ? red[lane] : 0.f;
#pragma unroll
    for (int off = 16; off; off >>= 1) gs += __shfl_xor_sync(0xffffffffu, gs, off);
    float invs = 1.f / gs;

    for (int i = tid; i < NCLS; i += 256) out[(size_t)b * NCLS + i] = expf(lr[i] - gm) * invs;
}

// ---------------- launch ----------------
extern "C" void kernel_launch(void* const* d_in, const int* in_sizes, int n_in,
                              void* d_out, int out_size) {
    const float* images = (const float*)d_in[0];
    const float* Wp  = (const float*)d_in[1];
    const float* bp  = (const float*)d_in[2];
    const float* cls = (const float*)d_in[3];
    const float* pos = (const float*)d_in[4];
    const float* ln1_g = (const float*)d_in[5];
    const float* ln1_b = (const float*)d_in[6];
    const float* Wq = (const float*)d_in[7];
    const float* bq = (const float*)d_in[8];
    const float* Wk = (const float*)d_in[9];
    const float* bk = (const float*)d_in[10];
    const float* Wv = (const float*)d_in[11];
    const float* bv = (const float*)d_in[12];
    const float* ln2_g = (const float*)d_in[13];
    const float* ln2_b = (const float*)d_in[14];
    const float* W1 = (const float*)d_in[15];
    const float* b1 = (const float*)d_in[16];
    const float* W2 = (const float*)d_in[17];
    const float* b2 = (const float*)d_in[18];
    const float* Wh = (const float*)d_in[19];
    const float* bh = (const float*)d_in[20];
    float* out = (float*)d_out;

    float *pP, *pX, *pH, *pQ, *pK, *pV, *pM, *pL;
    cudaGetSymbolAddress((void**)&pP, g_patches);
    cudaGetSymbolAddress((void**)&pX, g_x);
    cudaGetSymbolAddress((void**)&pH, g_h);
    cudaGetSymbolAddress((void**)&pQ, g_q);
    cudaGetSymbolAddress((void**)&pK, g_k);
    cudaGetSymbolAddress((void**)&pV, g_v);
    cudaGetSymbolAddress((void**)&pM, g_mlp);
    cudaGetSymbolAddress((void**)&pL, g_logits);

    cudaFuncSetAttribute(attn_kernel, cudaFuncAttributeMaxDynamicSharedMemorySize, ATTN_SMEM);

    // patch embedding
    patchify_kernel<<<(PTOT * DIM + 255) / 256, 256>>>(images, pP);
    sgemm_kernel<0><<<dim3(6, 49), 256>>>(pP, Wp, bp, pH, PTOT, DIM, DIM, DIM);
    assemble_kernel<<<(RTOT * DIM + 255) / 256, 256>>>(pH, cls, pos, pX);

    for (int l = 0; l < LL; l++) {
        ln_kernel<<<RTOT, 256>>>(pX, ln1_g + l * DIM, ln1_b + l * DIM, pH);
        qkv_kernel<<<dim3((RTOT + 63) / 64, NHD), 256>>>(
            pH,
            Wq + (size_t)l * NHD * HDD * HDD, bq + (size_t)l * NHD * HDD,
            Wk + (size_t)l * NHD * HDD * HDD, bk + (size_t)l * NHD * HDD,
            Wv + (size_t)l * NHD * HDD * HDD, bv + (size_t)l * NHD * HDD,
            pQ, pK, pV);
        attn_kernel<<<dim3((SS + 31) / 32, BB * NHD), 256, ATTN_SMEM>>>(pQ, pK, pV, pX);
        ln_kernel<<<RTOT, 256>>>(pX, ln2_g + l * DIM, ln2_b + l * DIM, pH);
        sgemm_kernel<1><<<dim3(24, 50), 256>>>(pH, W1 + (size_t)l * DIM * MLPD, b1 + (size_t)l * MLPD,
                                               pM, RTOT, MLPD, DIM, DIM);
        sgemm_kernel<2><<<dim3(6, 50), 256>>>(pM, W2 + (size_t)l * MLPD * DIM, b2 + (size_t)l * DIM,
                                              pX, RTOT, DIM, MLPD, MLPD);
    }

    // classifier head on CLS token (row stride = S*D)
    sgemm_kernel<0><<<dim3(8, 1), 256>>>(pX, Wh, bh, pL, BB, NCLS, DIM, SS * DIM);
    softmax_out_kernel<<<BB, 256>>>(pL, out);
}